// round 16
// baseline (speedup 1.0000x reference)
#include <cuda_runtime.h>
#include <cuda_bf16.h>
#include <cuda_fp16.h>
#include <cstdint>

#define N_NODES   10000
#define E_EDGES   160000
#define D_DIM     512
#define EDGE_DIM  128
#define L_LAYERS  3
#define LN_EPS    1e-5f

// ---------------- scratch ----------------
__device__ __align__(16) float g_agg[(size_t)N_NODES * D_DIM];
__device__ __align__(16) float g_h  [(size_t)N_NODES * D_DIM];
__device__ __align__(16) float g_t  [(size_t)N_NODES * D_DIM];
__device__ __align__(16) float g_g  [(size_t)N_NODES * D_DIM];
__device__ __align__(16) unsigned short g_EAh[(size_t)E_EDGES * EDGE_DIM];
__device__ __align__(16) unsigned short g_Weh[(size_t)L_LAYERS * EDGE_DIM * D_DIM];
__device__ __align__(16) unsigned short g_W1h[(size_t)L_LAYERS * D_DIM * D_DIM];
__device__ __align__(16) unsigned short g_W2h[(size_t)L_LAYERS * D_DIM * D_DIM];
__device__ __align__(16) unsigned short g_Wfh[(size_t)D_DIM * D_DIM];
__device__ int g_pos[N_NODES];
__device__ int g_perm[E_EDGES];
__device__ int g_sortedSrc[E_EDGES];
__device__ int g_sortedDst[E_EDGES];
__device__ int g_is64 = 1;
__device__ unsigned int g_barCnt[4];

// ---------------- helpers ----------------
__device__ __forceinline__ uint32_t smem_u32(const void* p) {
    uint32_t a;
    asm("{ .reg .u64 t; cvta.to.shared.u64 t, %1; cvt.u32.u64 %0, t; }" : "=r"(a) : "l"(p));
    return a;
}
__device__ __forceinline__ uint32_t pack_h(float a, float b) {
    uint32_t lo16 = __half_as_ushort(__float2half_rn(a));
    uint32_t hi16 = __half_as_ushort(__float2half_rn(b));
    return lo16 | (hi16 << 16);
}
__device__ __forceinline__ void ldmx4(uint32_t* r, uint32_t addr) {
    asm volatile("ldmatrix.sync.aligned.m8n8.x4.shared.b16 {%0,%1,%2,%3}, [%4];"
        : "=r"(r[0]), "=r"(r[1]), "=r"(r[2]), "=r"(r[3]) : "r"(addr));
}
__device__ __forceinline__ void ldmx4t(uint32_t* r, uint32_t addr) {
    asm volatile("ldmatrix.sync.aligned.m8n8.x4.trans.shared.b16 {%0,%1,%2,%3}, [%4];"
        : "=r"(r[0]), "=r"(r[1]), "=r"(r[2]), "=r"(r[3]) : "r"(addr));
}
__device__ __forceinline__ void mma_f16(float* c, const uint32_t* a, uint32_t b0, uint32_t b1) {
    asm volatile("mma.sync.aligned.m16n8k16.row.col.f32.f16.f16.f32 "
        "{%0,%1,%2,%3}, {%4,%5,%6,%7}, {%8,%9}, {%0,%1,%2,%3};"
        : "+f"(c[0]), "+f"(c[1]), "+f"(c[2]), "+f"(c[3])
        : "r"(a[0]), "r"(a[1]), "r"(a[2]), "r"(a[3]), "r"(b0), "r"(b1));
}
__device__ __forceinline__ void cp16(uint32_t dst, const void* src) {
    asm volatile("cp.async.cg.shared.global [%0], [%1], 16;" :: "r"(dst), "l"(src));
}
__device__ __forceinline__ void cp_commit() { asm volatile("cp.async.commit_group;"); }
__device__ __forceinline__ void cp_wait0()  { asm volatile("cp.async.wait_group 0;"); }

__device__ __forceinline__ void get_edge(const void* ei, int e, int& s, int& d) {
    if (g_is64) {
        const long long* p = (const long long*)ei;
        s = (int)p[e]; d = (int)p[E_EDGES + e];
    } else {
        const int* p = (const int*)ei;
        s = p[e]; d = p[E_EDGES + e];
    }
}

// ---------------- launch 0: fused counting sort ----------------
#define SORT_BLKS 148
__device__ __forceinline__ void grid_bar(int j) {
    __shared__ unsigned int s_target;
    __syncthreads();
    if (threadIdx.x == 0) {
        __threadfence();
        unsigned int my = atomicAdd(&g_barCnt[j], 1u);
        s_target = (my / SORT_BLKS + 1u) * SORT_BLKS;
    }
    __syncthreads();
    if (threadIdx.x == 0) {
        unsigned int v;
        do {
            asm volatile("ld.acquire.gpu.u32 %0, [%1];" : "=r"(v) : "l"(&g_barCnt[j]));
        } while (v < s_target);
    }
    __syncthreads();
}
__global__ void __launch_bounds__(256) fused_sort_kernel(const void* __restrict__ ei_raw) {
    const long long* ei64 = (const long long*)ei_raw;
    int idx = blockIdx.x * 256 + threadIdx.x;
    const int stride = SORT_BLKS * 256;
    for (int i = idx; i < N_NODES; i += stride) g_pos[i] = 0;
    bool bad = false;
    for (int i = idx; i < E_EDGES; i += stride) {
        long long v = ei64[i];
        if (v < 0 || v >= N_NODES) bad = true;
    }
    if (__syncthreads_or(bad)) { if (threadIdx.x == 0) g_is64 = 0; }
    grid_bar(0);
    for (int e = idx; e < E_EDGES; e += stride) {
        int s, d; get_edge(ei_raw, e, s, d);
        atomicAdd(&g_pos[d], 1);
    }
    grid_bar(1);
    if (blockIdx.x == 0) {
        const int T = 256, C = (N_NODES + T - 1) / T;
        __shared__ int sA[256], sB[256];
        int t = threadIdx.x, base = t * C, sum = 0;
        int local[C];
#pragma unroll
        for (int c = 0; c < C; c++) {
            int i = base + c;
            local[c] = (i < N_NODES) ? g_pos[i] : 0;
            sum += local[c];
        }
        sA[t] = sum; __syncthreads();
        int* cur = sA; int* nxt = sB;
        for (int off = 1; off < T; off <<= 1) {
            int v = cur[t];
            if (t >= off) v += cur[t - off];
            nxt[t] = v; __syncthreads();
            int* tmp = cur; cur = nxt; nxt = tmp;
        }
        int running = (t > 0) ? cur[t - 1] : 0;
#pragma unroll
        for (int c = 0; c < C; c++) {
            int i = base + c;
            if (i < N_NODES) g_pos[i] = running;
            running += local[c];
        }
    }
    grid_bar(2);
    for (int e = idx; e < E_EDGES; e += stride) {
        int s, d; get_edge(ei_raw, e, s, d);
        int pos = atomicAdd(&g_pos[d], 1);
        g_perm[pos] = e; g_sortedSrc[pos] = s; g_sortedDst[pos] = d;
    }
}

// ---------------- presplit helpers ----------------
__device__ __forceinline__ void round_store_h(float4 v, unsigned short* dst, int i) {
    uint2 ph;
    ph.x = pack_h(v.x, v.y); ph.y = pack_h(v.z, v.w);
    ((uint2*)dst)[i] = ph;
}

// ---------------- launch 1: edge fp16 round (sorted gather) ----------------
__global__ void presplit_edges_kernel(const float* __restrict__ ea) {
    int idx = blockIdx.x * blockDim.x + threadIdx.x;
    if (idx >= E_EDGES * (EDGE_DIM / 4)) return;
    int p = idx >> 5;
    int c4 = (idx & 31) * 4;
    int e = g_perm[p];
    float4 v = *(const float4*)(ea + (size_t)e * EDGE_DIM + c4);
    round_store_h(v, g_EAh, (int)(((size_t)p * EDGE_DIM + c4) >> 2));
}

// ---------------- launch 2: weights fp16 round + layer-0 agg init ----------------
#define WE4 (L_LAYERS * EDGE_DIM * D_DIM / 4)
#define W4  (L_LAYERS * D_DIM * D_DIM / 4)
#define WF4 (D_DIM * D_DIM / 4)
#define N4  (N_NODES * D_DIM / 4)
#define WE_BLKS (WE4 / 256)
#define W_BLKS  (W4 / 256)
#define WF_BLKS (WF4 / 256)
#define SC_BLKS ((N4 + 255) / 256)
#define WPRE_BLKS (WE_BLKS + 2 * W_BLKS + WF_BLKS + SC_BLKS)

__global__ void presplit_w_agg_kernel(const float* __restrict__ We,
                                      const float* __restrict__ W1,
                                      const float* __restrict__ W2,
                                      const float* __restrict__ Wf,
                                      const float* __restrict__ x,
                                      const float* __restrict__ eps,
                                      float* __restrict__ agg) {
    int b = blockIdx.x;
    int tid = threadIdx.x;
    if (b < WE_BLKS) {
        int i = b * 256 + tid;
        round_store_h(((const float4*)We)[i], g_Weh, i);
        return;
    }
    b -= WE_BLKS;
    if (b < W_BLKS) {
        int i = b * 256 + tid;
        round_store_h(((const float4*)W1)[i], g_W1h, i);
        return;
    }
    b -= W_BLKS;
    if (b < W_BLKS) {
        int i = b * 256 + tid;
        round_store_h(((const float4*)W2)[i], g_W2h, i);
        return;
    }
    b -= W_BLKS;
    if (b < WF_BLKS) {
        int i = b * 256 + tid;
        round_store_h(((const float4*)Wf)[i], g_Wfh, i);
        return;
    }
    b -= WF_BLKS;
    {
        int i = b * 256 + tid;
        if (i < N4) {
            float s = 1.0f + eps[0];
            float4 v = ((const float4*)x)[i];
            v.x *= s; v.y *= s; v.z *= s; v.w *= s;
            ((float4*)agg)[i] = v;
        }
    }
}

// ======================= EDGE kernel: single-stage full-tile fp16 =======================
// 128-row tile, 4wm x 2wn warps (MF=2, NF=8), K=128 staged entirely (A 34KB + B 34KB)
#define EP 136                                  // smem pitch (elems) for both A and B
#define E_STB (128 * EP * 2)                    // 34816: B tile base
#define SMEM_EDGE_T (2 * 128 * EP * 2)          // 69632 (Cs overlay = 128*136*4 = same)
#define CPITCH 136

__global__ void __launch_bounds__(256, 2) edge_mma_kernel(
        const unsigned short* __restrict__ Bh,
        const float* __restrict__ bias, const float* __restrict__ hbuf,
        float* __restrict__ out) {
    extern __shared__ char smc[];
    uint32_t sb = smem_u32(smc);
    float* Cs = (float*)smc;

    int tid  = threadIdx.x;
    int wid  = tid >> 5;
    int lane = tid & 31;
    int gid  = lane >> 2;
    int tig  = lane & 3;
    int wm   = wid >> 1;                 // 0..3
    int wn   = wid & 1;                  // 0..1
    int brow = blockIdx.y * 128;
    int bcol = blockIdx.x * 128;

    float acc[2][8][4];
#pragma unroll
    for (int i = 0; i < 2; i++)
#pragma unroll
        for (int j = 0; j < 8; j++)
#pragma unroll
            for (int q = 0; q < 4; q++) acc[i][j][q] = 0.f;

    // ---- single-stage load: A[128x128] + B[128x128] fp16 ----
    {
        int r = tid >> 1;                 // 0..127
        int cb = (tid & 1) * 64;          // col base
        const unsigned short* ap = g_EAh + (size_t)(brow + r) * EDGE_DIM + cb;
        const unsigned short* bp = Bh + (size_t)r * D_DIM + bcol + cb;
        uint32_t ad = sb + (uint32_t)(r * EP + cb) * 2;
        uint32_t bd = sb + E_STB + (uint32_t)(r * EP + cb) * 2;
#pragma unroll
        for (int j = 0; j < 8; j++) {
            cp16(ad + j * 16, ap + j * 8);
            cp16(bd + j * 16, bp + j * 8);
        }
        cp_commit();
    }
    cp_wait0();
    __syncthreads();

    // ---- compute: 8 k16 steps, uninterrupted ----
    int arow = ((lane >> 3) & 1) * 8 + (lane & 7);
    int acs  = (lane >> 4) * 8;
    int bkr  = ((lane >> 3) & 1) * 8 + (lane & 7);
    int bnc  = (lane >> 4) * 8;
#pragma unroll
    for (int ks = 0; ks < 128; ks += 16) {
        uint32_t bh[4][4];
#pragma unroll
        for (int pn = 0; pn < 4; pn++) {
            uint32_t bd = sb + E_STB + (uint32_t)((ks + bkr) * EP + wn * 64 + pn * 16 + bnc) * 2;
            ldmx4t(bh[pn], bd);
        }
#pragma unroll
        for (int mf = 0; mf < 2; mf++) {
            uint32_t ad = sb + (uint32_t)((wm * 32 + mf * 16 + arow) * EP + ks + acs) * 2;
            uint32_t ah[4];
            ldmx4(ah, ad);
#pragma unroll
            for (int nf = 0; nf < 8; nf++) {
                int pn = nf >> 1, sub = nf & 1;
                mma_f16(acc[mf][nf], ah, bh[pn][sub * 2], bh[pn][sub * 2 + 1]);
            }
        }
    }

    // ---- epilogue: stage to Cs, run-combined scatter ----
    __syncthreads();
#pragma unroll
    for (int mf = 0; mf < 2; mf++) {
        int rl = wm * 32 + mf * 16 + gid;
#pragma unroll
        for (int nf = 0; nf < 8; nf++) {
            int cl = wn * 64 + nf * 8 + 2 * tig;
            *(float2*)&Cs[rl * CPITCH + cl]       = make_float2(acc[mf][nf][0], acc[mf][nf][1]);
            *(float2*)&Cs[(rl + 8) * CPITCH + cl] = make_float2(acc[mf][nf][2], acc[mf][nf][3]);
        }
    }
    __syncthreads();
    int trow = (tid / 16) * 8;
    int tcol = (tid % 16) * 8;
    int colg = bcol + tcol;
    float bv[8];
    *(float4*)&bv[0] = *(const float4*)(bias + colg);
    *(float4*)&bv[4] = *(const float4*)(bias + colg + 4);
    float run[8];
    int prevDst = -1;
#pragma unroll
    for (int i = 0; i < 8; i++) {
        int r = brow + trow + i;
        int s = g_sortedSrc[r];
        int d = g_sortedDst[r];
        const float4* hp = (const float4*)(hbuf + (size_t)s * D_DIM + colg);
        float4 h0 = hp[0], h1 = hp[1];
        const float* cr = &Cs[(trow + i) * CPITCH + tcol];
        float m[8];
        m[0] = fmaxf(cr[0] + bv[0] + h0.x, 0.f);
        m[1] = fmaxf(cr[1] + bv[1] + h0.y, 0.f);
        m[2] = fmaxf(cr[2] + bv[2] + h0.z, 0.f);
        m[3] = fmaxf(cr[3] + bv[3] + h0.w, 0.f);
        m[4] = fmaxf(cr[4] + bv[4] + h1.x, 0.f);
        m[5] = fmaxf(cr[5] + bv[5] + h1.y, 0.f);
        m[6] = fmaxf(cr[6] + bv[6] + h1.z, 0.f);
        m[7] = fmaxf(cr[7] + bv[7] + h1.w, 0.f);
        if (d != prevDst) {
            if (prevDst >= 0) {
                float* ap = out + (size_t)prevDst * D_DIM + colg;
#pragma unroll
                for (int j = 0; j < 8; j++)
                    if (run[j] != 0.f) atomicAdd(&ap[j], run[j]);
            }
#pragma unroll
            for (int j = 0; j < 8; j++) run[j] = m[j];
            prevDst = d;
        } else {
#pragma unroll
            for (int j = 0; j < 8; j++) run[j] += m[j];
        }
    }
    if (prevDst >= 0) {
        float* ap = out + (size_t)prevDst * D_DIM + colg;
#pragma unroll
        for (int j = 0; j < 8; j++)
            if (run[j] != 0.f) atomicAdd(&ap[j], run[j]);
    }
}

// ======================= NODE kernel: chunked fp16 hi/lo (as R15) =======================
#define APITCH 40
#define BPITCH 136
#define N_ST_ALO (64 * APITCH * 2)
#define N_ST_B   (2 * 64 * APITCH * 2)
#define N_STG    (N_ST_B + 32 * BPITCH * 2)     // 18944
#define SMEM_NODE_T (2 * N_STG)                  // 37888

__global__ void __launch_bounds__(256, 3) node_mma_kernel(
        const float* __restrict__ A,
        const unsigned short* __restrict__ Bh,
        const float* __restrict__ bias,
        float* __restrict__ out, int M, int doRelu) {
    const int K = D_DIM;
    extern __shared__ char smc[];
    uint32_t sb = smem_u32(smc);

    int tid  = threadIdx.x;
    int wid  = tid >> 5;
    int lane = tid & 31;
    int gid  = lane >> 2;
    int tig  = lane & 3;
    int wm   = wid >> 2;                 // 0..1
    int wn   = wid & 3;                  // 0..3
    int brow = blockIdx.y * 64;
    int bcol = blockIdx.x * 128;

    float acc[2][4][4];
#pragma unroll
    for (int i = 0; i < 2; i++)
#pragma unroll
        for (int j = 0; j < 4; j++)
#pragma unroll
            for (int q = 0; q < 4; q++) acc[i][j][q] = 0.f;

    int aRow = tid >> 2, aOff = (tid & 3) * 8;
    int bKr  = tid >> 3, bSeg = tid & 7;
    int gr = brow + aRow;
    const float* ApF = A + (size_t)(gr < M ? gr : 0) * K + aOff;
    const unsigned short* Bp = Bh + (size_t)bKr * D_DIM + bcol + bSeg * 16;
    uint32_t aRel = (uint32_t)(aRow * APITCH + aOff) * 2;
    uint32_t bRel = N_ST_B + (uint32_t)(bKr * BPITCH + bSeg * 16) * 2;

    const int NC = K >> 5;
    float4 stA[2];

    {
        stA[0] = *(const float4*)(ApF);
        stA[1] = *(const float4*)(ApF + 4);
        cp16(sb + bRel,      Bp);
        cp16(sb + bRel + 16, Bp + 8);
        cp_commit();
        const float* vv = (const float*)stA;
        uint32_t ph[4], pl[4];
#pragma unroll
        for (int j = 0; j < 4; j++) {
            float f0 = vv[2 * j], f1 = vv[2 * j + 1];
            float h0 = __half2float(__float2half_rn(f0));
            float h1 = __half2float(__float2half_rn(f1));
            ph[j] = pack_h(f0, f1);
            pl[j] = pack_h(f0 - h0, f1 - h1);
        }
        *(int4*)(smc + aRel)            = *(int4*)&ph[0];
        *(int4*)(smc + aRel + N_ST_ALO) = *(int4*)&pl[0];
    }

    for (int c = 0; c < NC; c++) {
        uint32_t so = (c & 1) ? N_STG : 0;
        uint32_t no = so ^ N_STG;
        cp_wait0();
        __syncthreads();
        if (c + 1 < NC) {
            int k1 = (c + 1) * 32;
            stA[0] = *(const float4*)(ApF + k1);
            stA[1] = *(const float4*)(ApF + k1 + 4);
            const unsigned short* bp = Bp + (size_t)(c + 1) * 32 * D_DIM;
            cp16(sb + no + bRel,      bp);
            cp16(sb + no + bRel + 16, bp + 8);
            cp_commit();
        }
#pragma unroll
        for (int ks = 0; ks < 32; ks += 16) {
            uint32_t bh[2][4];
            int bkrow = ks + ((lane >> 3) & 1) * 8 + (lane & 7);
            int bnc   = (lane >> 4) * 8;
#pragma unroll
            for (int pn = 0; pn < 2; pn++) {
                uint32_t bd = sb + so + N_ST_B + (uint32_t)(bkrow * BPITCH + wn * 32 + pn * 16 + bnc) * 2;
                ldmx4t(bh[pn], bd);
            }
            int arow = ((lane >> 3) & 1) * 8 + (lane & 7);
            int akc  = ks + (lane >> 4) * 8;
#pragma unroll
            for (int mf = 0; mf < 2; mf++) {
                uint32_t ad = sb + so + (uint32_t)((wm * 32 + mf * 16 + arow) * APITCH + akc) * 2;
                uint32_t ah[4], al[4];
                ldmx4(ah, ad);
#pragma unroll
                for (int nf = 0; nf < 4; nf++) {
                    int pn = nf >> 1, sub = nf & 1;
                    mma_f16(acc[mf][nf], ah, bh[pn][sub * 2], bh[pn][sub * 2 + 1]);
                }
                ldmx4(al, ad + N_ST_ALO);
#pragma unroll
                for (int nf = 0; nf < 4; nf++) {
                    int pn = nf >> 1, sub = nf & 1;
                    mma_f16(acc[mf][nf], al, bh[pn][sub * 2], bh[pn][sub * 2 + 1]);
                }
            }
        }
        if (c + 1 < NC) {
            const float* vv = (const float*)stA;
            uint32_t ph[4], pl[4];
#pragma unroll
            for (int j = 0; j < 4; j++) {
                float f0 = vv[2 * j], f1 = vv[2 * j + 1];
                float h0 = __half2float(__float2half_rn(f0));
                float h1 = __half2float(__float2half_rn(f1));
                ph[j] = pack_h(f0, f1);
                pl[j] = pack_h(f0 - h0, f1 - h1);
            }
            *(int4*)(smc + no + aRel)            = *(int4*)&ph[0];
            *(int4*)(smc + no + aRel + N_ST_ALO) = *(int4*)&pl[0];
        }
    }

#pragma unroll
    for (int mf = 0; mf < 2; mf++) {
        int r0 = brow + wm * 32 + mf * 16 + gid;
#pragma unroll
        for (int nf = 0; nf < 4; nf++) {
            int col = bcol + wn * 32 + nf * 8 + 2 * tig;
            float b0 = bias[col], b1 = bias[col + 1];
            float v0 = acc[mf][nf][0] + b0;
            float v1 = acc[mf][nf][1] + b1;
            float v2 = acc[mf][nf][2] + b0;
            float v3 = acc[mf][nf][3] + b1;
            if (doRelu) {
                v0 = fmaxf(v0, 0.f); v1 = fmaxf(v1, 0.f);
                v2 = fmaxf(v2, 0.f); v3 = fmaxf(v3, 0.f);
            }
            if (r0 < M)     *(float2*)(out + (size_t)r0 * D_DIM + col)       = make_float2(v0, v1);
            if (r0 + 8 < M) *(float2*)(out + (size_t)(r0 + 8) * D_DIM + col) = make_float2(v2, v3);
        }
    }
}

// ---------------- LayerNorm (+ fused agg init) ----------------
__global__ void __launch_bounds__(128) layernorm_kernel(const float* __restrict__ g,
                                                        const float* __restrict__ gamma,
                                                        const float* __restrict__ beta,
                                                        float* __restrict__ out,
                                                        const float* __restrict__ epsArr,
                                                        int nextLayer,
                                                        float* __restrict__ agg) {
    int row = blockIdx.x, t = threadIdx.x;
    const float4* gp = (const float4*)(g + (size_t)row * D_DIM);
    float4 v = gp[t];
    float s  = v.x + v.y + v.z + v.w;
    float sq = v.x * v.x + v.y * v.y + v.z * v.z + v.w * v.w;
#pragma unroll
    for (int o = 16; o > 0; o >>= 1) {
        s  += __shfl_xor_sync(0xffffffffu, s, o);
        sq += __shfl_xor_sync(0xffffffffu, sq, o);
    }
    __shared__ float red[8];
    int w = t >> 5;
    if ((t & 31) == 0) { red[w] = s; red[4 + w] = sq; }
    __syncthreads();
    s  = red[0] + red[1] + red[2] + red[3];
    sq = red[4] + red[5] + red[6] + red[7];
    float mu  = s * (1.0f / D_DIM);
    float var = sq * (1.0f / D_DIM) - mu * mu;
    float inv = rsqrtf(var + LN_EPS);
    float4 ga = *(const float4*)(gamma + t * 4);
    float4 be = *(const float4*)(beta + t * 4);
    float4 o;
    o.x = (v.x - mu) * inv * ga.x + be.x;
    o.y = (v.y - mu) * inv * ga.y + be.y;
    o.z = (v.z - mu) * inv * ga.z + be.z;
    o.w = (v.w - mu) * inv * ga.w + be.w;
    ((float4*)(out + (size_t)row * D_DIM))[t] = o;
    if (nextLayer < L_LAYERS) {
        float sc = 1.0f + epsArr[nextLayer];
        float4 a;
        a.x = o.x * sc; a.y = o.y * sc; a.z = o.z * sc; a.w = o.w * sc;
        ((float4*)(agg + (size_t)row * D_DIM))[t] = a;
    }
}

// ---------------- launch ----------------
extern "C" void kernel_launch(void* const* d_in, const int* in_sizes, int n_in,
                              void* d_out, int out_size) {
    const float* x     = (const float*)d_in[0];
    const void*  ei    = d_in[1];
    const float* ea    = (const float*)d_in[2];
    const float* We    = (const float*)d_in[3];
    const float* be    = (const float*)d_in[4];
    const float* eps   = (const float*)d_in[5];
    const float* W1    = (const float*)d_in[6];
    const float* b1    = (const float*)d_in[7];
    const float* W2    = (const float*)d_in[8];
    const float* b2    = (const float*)d_in[9];
    const float* gamma = (const float*)d_in[10];
    const float* beta  = (const float*)d_in[11];
    const float* Wf    = (const float*)d_in[12];
    const float* bf    = (const float*)d_in[13];
    float* out = (float*)d_out;

    float *agg, *h, *t, *gg;
    unsigned short *Weh, *W1h, *W2h, *Wfh;
    cudaGetSymbolAddress((void**)&agg, g_agg);
    cudaGetSymbolAddress((void**)&h,   g_h);
    cudaGetSymbolAddress((void**)&t,   g_t);
    cudaGetSymbolAddress((void**)&gg,  g_g);
    cudaGetSymbolAddress((void**)&Weh, g_Weh);
    cudaGetSymbolAddress((void**)&W1h, g_W1h);
    cudaGetSymbolAddress((void**)&W2h, g_W2h);
    cudaGetSymbolAddress((void**)&Wfh, g_Wfh);

    cudaFuncSetAttribute(edge_mma_kernel, cudaFuncAttributeMaxDynamicSharedMemorySize, SMEM_EDGE_T);
    cudaFuncSetAttribute(node_mma_kernel, cudaFuncAttributeMaxDynamicSharedMemorySize, SMEM_NODE_T);

    // ---- preprocessing: edge MMA stays at launch index 3 (profiled) ----
    fused_sort_kernel<<<SORT_BLKS, 256>>>(ei);                                   // 0
    presplit_edges_kernel<<<E_EDGES * (EDGE_DIM / 4) / 256, 256>>>(ea);          // 1
    presplit_w_agg_kernel<<<WPRE_BLKS, 256>>>(We, W1, W2, Wf, x, eps, agg);      // 2

    dim3 gEdge(D_DIM / 128, E_EDGES / 128);                 // (4, 1250)
    dim3 gNode(D_DIM / 128, (N_NODES + 63) / 64);           // (4, 157)
    const size_t WSTEP = (size_t)D_DIM * D_DIM;

    for (int l = 0; l < L_LAYERS; l++) {
        const float* hCur = (l == 0) ? x : h;
        edge_mma_kernel<<<gEdge, 256, SMEM_EDGE_T>>>(                            // 3 = profiled
            Weh + (size_t)l * EDGE_DIM * D_DIM,
            be + (size_t)l * D_DIM, hCur, agg);
        node_mma_kernel<<<gNode, 256, SMEM_NODE_T>>>(
            agg, W1h + l * WSTEP, b1 + (size_t)l * D_DIM, t, N_NODES, 1);
        node_mma_kernel<<<gNode, 256, SMEM_NODE_T>>>(
            t, W2h + l * WSTEP, b2 + (size_t)l * D_DIM, gg, N_NODES, 1);
        layernorm_kernel<<<N_NODES, 128>>>(gg, gamma + (size_t)l * D_DIM,
                                           beta + (size_t)l * D_DIM, h,
                                           eps, l + 1, agg);
    }
    node_mma_kernel<<<gNode, 256, SMEM_NODE_T>>>(h, Wfh, bf, out, N_NODES, 0);
}

// round 17
// speedup vs baseline: 1.1178x; 1.1178x over previous
#include <cuda_runtime.h>
#include <cuda_bf16.h>
#include <cuda_fp16.h>
#include <cstdint>

#define N_NODES   10000
#define E_EDGES   160000
#define D_DIM     512
#define EDGE_DIM  128
#define L_LAYERS  3
#define LN_EPS    1e-5f

// ---------------- scratch ----------------
__device__ __align__(16) float g_agg[(size_t)N_NODES * D_DIM];
__device__ __align__(16) float g_h  [(size_t)N_NODES * D_DIM];
__device__ __align__(16) float g_t  [(size_t)N_NODES * D_DIM];
__device__ __align__(16) float g_g  [(size_t)N_NODES * D_DIM];
__device__ __align__(16) unsigned short g_EAh[(size_t)E_EDGES * EDGE_DIM];
__device__ __align__(16) unsigned short g_Weh[(size_t)L_LAYERS * EDGE_DIM * D_DIM];
__device__ __align__(16) unsigned short g_W1h[(size_t)L_LAYERS * D_DIM * D_DIM];
__device__ __align__(16) unsigned short g_W2h[(size_t)L_LAYERS * D_DIM * D_DIM];
__device__ __align__(16) unsigned short g_Wfh[(size_t)D_DIM * D_DIM];
__device__ int g_pos[N_NODES];
__device__ int g_perm[E_EDGES];
__device__ int g_sortedSrc[E_EDGES];
__device__ int g_sortedDst[E_EDGES];
__device__ int g_is64 = 1;
__device__ unsigned int g_barCnt[4];

// ---------------- helpers ----------------
__device__ __forceinline__ uint32_t smem_u32(const void* p) {
    uint32_t a;
    asm("{ .reg .u64 t; cvta.to.shared.u64 t, %1; cvt.u32.u64 %0, t; }" : "=r"(a) : "l"(p));
    return a;
}
__device__ __forceinline__ uint32_t pack_h(float a, float b) {
    uint32_t lo16 = __half_as_ushort(__float2half_rn(a));
    uint32_t hi16 = __half_as_ushort(__float2half_rn(b));
    return lo16 | (hi16 << 16);
}
__device__ __forceinline__ void ldmx4(uint32_t* r, uint32_t addr) {
    asm volatile("ldmatrix.sync.aligned.m8n8.x4.shared.b16 {%0,%1,%2,%3}, [%4];"
        : "=r"(r[0]), "=r"(r[1]), "=r"(r[2]), "=r"(r[3]) : "r"(addr));
}
__device__ __forceinline__ void ldmx4t(uint32_t* r, uint32_t addr) {
    asm volatile("ldmatrix.sync.aligned.m8n8.x4.trans.shared.b16 {%0,%1,%2,%3}, [%4];"
        : "=r"(r[0]), "=r"(r[1]), "=r"(r[2]), "=r"(r[3]) : "r"(addr));
}
__device__ __forceinline__ void mma_f16(float* c, const uint32_t* a, uint32_t b0, uint32_t b1) {
    asm volatile("mma.sync.aligned.m16n8k16.row.col.f32.f16.f16.f32 "
        "{%0,%1,%2,%3}, {%4,%5,%6,%7}, {%8,%9}, {%0,%1,%2,%3};"
        : "+f"(c[0]), "+f"(c[1]), "+f"(c[2]), "+f"(c[3])
        : "r"(a[0]), "r"(a[1]), "r"(a[2]), "r"(a[3]), "r"(b0), "r"(b1));
}
__device__ __forceinline__ void cp16(uint32_t dst, const void* src) {
    asm volatile("cp.async.cg.shared.global [%0], [%1], 16;" :: "r"(dst), "l"(src));
}
__device__ __forceinline__ void cp_commit() { asm volatile("cp.async.commit_group;"); }
__device__ __forceinline__ void cp_wait0()  { asm volatile("cp.async.wait_group 0;"); }
__device__ __forceinline__ void cp_wait1()  { asm volatile("cp.async.wait_group 1;"); }

__device__ __forceinline__ void get_edge(const void* ei, int e, int& s, int& d) {
    if (g_is64) {
        const long long* p = (const long long*)ei;
        s = (int)p[e]; d = (int)p[E_EDGES + e];
    } else {
        const int* p = (const int*)ei;
        s = p[e]; d = p[E_EDGES + e];
    }
}

// ---------------- launch 0: fused counting sort ----------------
#define SORT_BLKS 148
__device__ __forceinline__ void grid_bar(int j) {
    __shared__ unsigned int s_target;
    __syncthreads();
    if (threadIdx.x == 0) {
        __threadfence();
        unsigned int my = atomicAdd(&g_barCnt[j], 1u);
        s_target = (my / SORT_BLKS + 1u) * SORT_BLKS;
    }
    __syncthreads();
    if (threadIdx.x == 0) {
        unsigned int v;
        do {
            asm volatile("ld.acquire.gpu.u32 %0, [%1];" : "=r"(v) : "l"(&g_barCnt[j]));
        } while (v < s_target);
    }
    __syncthreads();
}
__global__ void __launch_bounds__(256) fused_sort_kernel(const void* __restrict__ ei_raw) {
    const long long* ei64 = (const long long*)ei_raw;
    int idx = blockIdx.x * 256 + threadIdx.x;
    const int stride = SORT_BLKS * 256;
    for (int i = idx; i < N_NODES; i += stride) g_pos[i] = 0;
    bool bad = false;
    for (int i = idx; i < E_EDGES; i += stride) {
        long long v = ei64[i];
        if (v < 0 || v >= N_NODES) bad = true;
    }
    if (__syncthreads_or(bad)) { if (threadIdx.x == 0) g_is64 = 0; }
    grid_bar(0);
    for (int e = idx; e < E_EDGES; e += stride) {
        int s, d; get_edge(ei_raw, e, s, d);
        atomicAdd(&g_pos[d], 1);
    }
    grid_bar(1);
    if (blockIdx.x == 0) {
        const int T = 256, C = (N_NODES + T - 1) / T;
        __shared__ int sA[256], sB[256];
        int t = threadIdx.x, base = t * C, sum = 0;
        int local[C];
#pragma unroll
        for (int c = 0; c < C; c++) {
            int i = base + c;
            local[c] = (i < N_NODES) ? g_pos[i] : 0;
            sum += local[c];
        }
        sA[t] = sum; __syncthreads();
        int* cur = sA; int* nxt = sB;
        for (int off = 1; off < T; off <<= 1) {
            int v = cur[t];
            if (t >= off) v += cur[t - off];
            nxt[t] = v; __syncthreads();
            int* tmp = cur; cur = nxt; nxt = tmp;
        }
        int running = (t > 0) ? cur[t - 1] : 0;
#pragma unroll
        for (int c = 0; c < C; c++) {
            int i = base + c;
            if (i < N_NODES) g_pos[i] = running;
            running += local[c];
        }
    }
    grid_bar(2);
    for (int e = idx; e < E_EDGES; e += stride) {
        int s, d; get_edge(ei_raw, e, s, d);
        int pos = atomicAdd(&g_pos[d], 1);
        g_perm[pos] = e; g_sortedSrc[pos] = s; g_sortedDst[pos] = d;
    }
}

// ---------------- presplit helpers ----------------
__device__ __forceinline__ void round_store_h(float4 v, unsigned short* dst, int i) {
    uint2 ph;
    ph.x = pack_h(v.x, v.y); ph.y = pack_h(v.z, v.w);
    ((uint2*)dst)[i] = ph;
}

// ---------------- launch 1: edge fp16 round (sorted gather) ----------------
__global__ void presplit_edges_kernel(const float* __restrict__ ea) {
    int idx = blockIdx.x * blockDim.x + threadIdx.x;
    if (idx >= E_EDGES * (EDGE_DIM / 4)) return;
    int p = idx >> 5;
    int c4 = (idx & 31) * 4;
    int e = g_perm[p];
    float4 v = *(const float4*)(ea + (size_t)e * EDGE_DIM + c4);
    round_store_h(v, g_EAh, (int)(((size_t)p * EDGE_DIM + c4) >> 2));
}

// ---------------- launch 2: weights fp16 round + layer-0 agg init ----------------
#define WE4 (L_LAYERS * EDGE_DIM * D_DIM / 4)
#define W4  (L_LAYERS * D_DIM * D_DIM / 4)
#define WF4 (D_DIM * D_DIM / 4)
#define N4  (N_NODES * D_DIM / 4)
#define WE_BLKS (WE4 / 256)
#define W_BLKS  (W4 / 256)
#define WF_BLKS (WF4 / 256)
#define SC_BLKS ((N4 + 255) / 256)
#define WPRE_BLKS (WE_BLKS + 2 * W_BLKS + WF_BLKS + SC_BLKS)

__global__ void presplit_w_agg_kernel(const float* __restrict__ We,
                                      const float* __restrict__ W1,
                                      const float* __restrict__ W2,
                                      const float* __restrict__ Wf,
                                      const float* __restrict__ x,
                                      const float* __restrict__ eps,
                                      float* __restrict__ agg) {
    int b = blockIdx.x;
    int tid = threadIdx.x;
    if (b < WE_BLKS) {
        int i = b * 256 + tid;
        round_store_h(((const float4*)We)[i], g_Weh, i);
        return;
    }
    b -= WE_BLKS;
    if (b < W_BLKS) {
        int i = b * 256 + tid;
        round_store_h(((const float4*)W1)[i], g_W1h, i);
        return;
    }
    b -= W_BLKS;
    if (b < W_BLKS) {
        int i = b * 256 + tid;
        round_store_h(((const float4*)W2)[i], g_W2h, i);
        return;
    }
    b -= W_BLKS;
    if (b < WF_BLKS) {
        int i = b * 256 + tid;
        round_store_h(((const float4*)Wf)[i], g_Wfh, i);
        return;
    }
    b -= WF_BLKS;
    {
        int i = b * 256 + tid;
        if (i < N4) {
            float s = 1.0f + eps[0];
            float4 v = ((const float4*)x)[i];
            v.x *= s; v.y *= s; v.z *= s; v.w *= s;
            ((float4*)agg)[i] = v;
        }
    }
}

// ======================= EDGE kernel: 3-stage pipelined fp16 =======================
// 128-row tile, 4wm x 2wn warps (MF=2, NF=8), K=128 in 4 chunks of 32, 3 SMEM stages
#define EAPITCH 40
#define EBPITCH 136
#define E_STB (128 * EAPITCH * 2)               // 10240
#define E_STG (E_STB + 32 * EBPITCH * 2)        // 18944; 3 stages = 56832
#define CPITCH 136
#define SMEM_EDGE_T (128 * CPITCH * 4)          // 69632 (Cs overlay; >= 3*E_STG)

__global__ void __launch_bounds__(256, 2) edge_mma_kernel(
        const unsigned short* __restrict__ Bh,
        const float* __restrict__ bias, const float* __restrict__ hbuf,
        float* __restrict__ out) {
    extern __shared__ char smc[];
    uint32_t sb = smem_u32(smc);
    float* Cs = (float*)smc;

    int tid  = threadIdx.x;
    int wid  = tid >> 5;
    int lane = tid & 31;
    int gid  = lane >> 2;
    int tig  = lane & 3;
    int wm   = wid >> 1;                 // 0..3
    int wn   = wid & 1;                  // 0..1
    int brow = blockIdx.y * 128;
    int bcol = blockIdx.x * 128;

    float acc[2][8][4];
#pragma unroll
    for (int i = 0; i < 2; i++)
#pragma unroll
        for (int j = 0; j < 8; j++)
#pragma unroll
            for (int q = 0; q < 4; q++) acc[i][j][q] = 0.f;

    int aRow = tid >> 1, aOff = (tid & 1) * 16;
    int bKr  = tid >> 3, bSeg = tid & 7;
    const unsigned short* ApH = g_EAh + (size_t)(brow + aRow) * EDGE_DIM + aOff;
    const unsigned short* Bp  = Bh + (size_t)bKr * D_DIM + bcol + bSeg * 16;
    uint32_t aRel = (uint32_t)(aRow * EAPITCH + aOff) * 2;
    uint32_t bRel = E_STB + (uint32_t)(bKr * EBPITCH + bSeg * 16) * 2;

    // ---- prologue: issue chunks 0 and 1 ----
#pragma unroll
    for (int p = 0; p < 2; p++) {
        uint32_t off = p * E_STG;
        cp16(sb + off + aRel,      ApH + p * 32);
        cp16(sb + off + aRel + 16, ApH + p * 32 + 8);
        cp16(sb + off + bRel,      Bp + (size_t)p * 32 * D_DIM);
        cp16(sb + off + bRel + 16, Bp + (size_t)p * 32 * D_DIM + 8);
        cp_commit();
    }

    const int NC = 4;   // K=128 / 32
#pragma unroll
    for (int c = 0; c < NC; c++) {
        uint32_t so = (uint32_t)(c % 3) * E_STG;
        if (c == NC - 1) cp_wait0(); else cp_wait1();
        __syncthreads();
        if (c + 2 < NC) {
            uint32_t no = (uint32_t)((c + 2) % 3) * E_STG;
            int k2 = (c + 2) * 32;
            cp16(sb + no + aRel,      ApH + k2);
            cp16(sb + no + aRel + 16, ApH + k2 + 8);
            cp16(sb + no + bRel,      Bp + (size_t)k2 * D_DIM);
            cp16(sb + no + bRel + 16, Bp + (size_t)k2 * D_DIM + 8);
            cp_commit();
        }
        // ---- compute: 2 k16 steps ----
#pragma unroll
        for (int ks = 0; ks < 32; ks += 16) {
            uint32_t bh[4][4];
            int bkrow = ks + ((lane >> 3) & 1) * 8 + (lane & 7);
            int bnc   = (lane >> 4) * 8;
#pragma unroll
            for (int pn = 0; pn < 4; pn++) {
                uint32_t bd = sb + so + E_STB + (uint32_t)(bkrow * EBPITCH + wn * 64 + pn * 16 + bnc) * 2;
                ldmx4t(bh[pn], bd);
            }
            int arow = ((lane >> 3) & 1) * 8 + (lane & 7);
            int akc  = ks + (lane >> 4) * 8;
#pragma unroll
            for (int mf = 0; mf < 2; mf++) {
                uint32_t ad = sb + so + (uint32_t)((wm * 32 + mf * 16 + arow) * EAPITCH + akc) * 2;
                uint32_t ah[4];
                ldmx4(ah, ad);
#pragma unroll
                for (int nf = 0; nf < 8; nf++) {
                    int pn = nf >> 1, sub = nf & 1;
                    mma_f16(acc[mf][nf], ah, bh[pn][sub * 2], bh[pn][sub * 2 + 1]);
                }
            }
        }
    }

    // ---- epilogue: stage to Cs overlay, run-combined scatter ----
    __syncthreads();
#pragma unroll
    for (int mf = 0; mf < 2; mf++) {
        int rl = wm * 32 + mf * 16 + gid;
#pragma unroll
        for (int nf = 0; nf < 8; nf++) {
            int cl = wn * 64 + nf * 8 + 2 * tig;
            *(float2*)&Cs[rl * CPITCH + cl]       = make_float2(acc[mf][nf][0], acc[mf][nf][1]);
            *(float2*)&Cs[(rl + 8) * CPITCH + cl] = make_float2(acc[mf][nf][2], acc[mf][nf][3]);
        }
    }
    __syncthreads();
    int trow = (tid / 16) * 8;
    int tcol = (tid % 16) * 8;
    int colg = bcol + tcol;
    float bv[8];
    *(float4*)&bv[0] = *(const float4*)(bias + colg);
    *(float4*)&bv[4] = *(const float4*)(bias + colg + 4);
    float run[8];
    int prevDst = -1;
#pragma unroll
    for (int i = 0; i < 8; i++) {
        int r = brow + trow + i;
        int s = g_sortedSrc[r];
        int d = g_sortedDst[r];
        const float4* hp = (const float4*)(hbuf + (size_t)s * D_DIM + colg);
        float4 h0 = hp[0], h1 = hp[1];
        const float* cr = &Cs[(trow + i) * CPITCH + tcol];
        float m[8];
        m[0] = fmaxf(cr[0] + bv[0] + h0.x, 0.f);
        m[1] = fmaxf(cr[1] + bv[1] + h0.y, 0.f);
        m[2] = fmaxf(cr[2] + bv[2] + h0.z, 0.f);
        m[3] = fmaxf(cr[3] + bv[3] + h0.w, 0.f);
        m[4] = fmaxf(cr[4] + bv[4] + h1.x, 0.f);
        m[5] = fmaxf(cr[5] + bv[5] + h1.y, 0.f);
        m[6] = fmaxf(cr[6] + bv[6] + h1.z, 0.f);
        m[7] = fmaxf(cr[7] + bv[7] + h1.w, 0.f);
        if (d != prevDst) {
            if (prevDst >= 0) {
                float* ap = out + (size_t)prevDst * D_DIM + colg;
#pragma unroll
                for (int j = 0; j < 8; j++)
                    if (run[j] != 0.f) atomicAdd(&ap[j], run[j]);
            }
#pragma unroll
            for (int j = 0; j < 8; j++) run[j] = m[j];
            prevDst = d;
        } else {
#pragma unroll
            for (int j = 0; j < 8; j++) run[j] += m[j];
        }
    }
    if (prevDst >= 0) {
        float* ap = out + (size_t)prevDst * D_DIM + colg;
#pragma unroll
        for (int j = 0; j < 8; j++)
            if (run[j] != 0.f) atomicAdd(&ap[j], run[j]);
    }
}

// ======================= NODE kernel: chunked fp16 hi/lo (R15-proven) =======================
#define APITCH 40
#define BPITCH 136
#define N_ST_ALO (64 * APITCH * 2)
#define N_ST_B   (2 * 64 * APITCH * 2)
#define N_STG    (N_ST_B + 32 * BPITCH * 2)     // 18944
#define SMEM_NODE_T (2 * N_STG)                  // 37888

__global__ void __launch_bounds__(256, 3) node_mma_kernel(
        const float* __restrict__ A,
        const unsigned short* __restrict__ Bh,
        const float* __restrict__ bias,
        float* __restrict__ out, int M, int doRelu) {
    const int K = D_DIM;
    extern __shared__ char smc[];
    uint32_t sb = smem_u32(smc);

    int tid  = threadIdx.x;
    int wid  = tid >> 5;
    int lane = tid & 31;
    int gid  = lane >> 2;
    int tig  = lane & 3;
    int wm   = wid >> 2;
    int wn   = wid & 3;
    int brow = blockIdx.y * 64;
    int bcol = blockIdx.x * 128;

    float acc[2][4][4];
#pragma unroll
    for (int i = 0; i < 2; i++)
#pragma unroll
        for (int j = 0; j < 4; j++)
#pragma unroll
            for (int q = 0; q < 4; q++) acc[i][j][q] = 0.f;

    int aRow = tid >> 2, aOff = (tid & 3) * 8;
    int bKr  = tid >> 3, bSeg = tid & 7;
    int gr = brow + aRow;
    const float* ApF = A + (size_t)(gr < M ? gr : 0) * K + aOff;
    const unsigned short* Bp = Bh + (size_t)bKr * D_DIM + bcol + bSeg * 16;
    uint32_t aRel = (uint32_t)(aRow * APITCH + aOff) * 2;
    uint32_t bRel = N_ST_B + (uint32_t)(bKr * BPITCH + bSeg * 16) * 2;

    const int NC = K >> 5;
    float4 stA[2];

    {
        stA[0] = *(const float4*)(ApF);
        stA[1] = *(const float4*)(ApF + 4);
        cp16(sb + bRel,      Bp);
        cp16(sb + bRel + 16, Bp + 8);
        cp_commit();
        const float* vv = (const float*)stA;
        uint32_t ph[4], pl[4];
#pragma unroll
        for (int j = 0; j < 4; j++) {
            float f0 = vv[2 * j], f1 = vv[2 * j + 1];
            float h0 = __half2float(__float2half_rn(f0));
            float h1 = __half2float(__float2half_rn(f1));
            ph[j] = pack_h(f0, f1);
            pl[j] = pack_h(f0 - h0, f1 - h1);
        }
        *(int4*)(smc + aRel)            = *(int4*)&ph[0];
        *(int4*)(smc + aRel + N_ST_ALO) = *(int4*)&pl[0];
    }

    for (int c = 0; c < NC; c++) {
        uint32_t so = (c & 1) ? N_STG : 0;
        uint32_t no = so ^ N_STG;
        cp_wait0();
        __syncthreads();
        if (c + 1 < NC) {
            int k1 = (c + 1) * 32;
            stA[0] = *(const float4*)(ApF + k1);
            stA[1] = *(const float4*)(ApF + k1 + 4);
            const unsigned short* bp = Bp + (size_t)(c + 1) * 32 * D_DIM;
            cp16(sb + no + bRel,      bp);
            cp16(sb + no + bRel + 16, bp + 8);
            cp_commit();
        }
#pragma unroll
        for (int ks = 0; ks < 32; ks += 16) {
            uint32_t bh[2][4];
            int bkrow = ks + ((lane >> 3) & 1) * 8 + (lane & 7);
            int bnc   = (lane >> 4) * 8;
#pragma unroll
            for (int pn = 0; pn < 2; pn++) {
                uint32_t bd = sb + so + N_ST_B + (uint32_t)(bkrow * BPITCH + wn * 32 + pn * 16 + bnc) * 2;
                ldmx4t(bh[pn], bd);
            }
            int arow = ((lane >> 3) & 1) * 8 + (lane & 7);
            int akc  = ks + (lane >> 4) * 8;
#pragma unroll
            for (int mf = 0; mf < 2; mf++) {
                uint32_t ad = sb + so + (uint32_t)((wm * 32 + mf * 16 + arow) * APITCH + akc) * 2;
                uint32_t ah[4], al[4];
                ldmx4(ah, ad);
#pragma unroll
                for (int nf = 0; nf < 4; nf++) {
                    int pn = nf >> 1, sub = nf & 1;
                    mma_f16(acc[mf][nf], ah, bh[pn][sub * 2], bh[pn][sub * 2 + 1]);
                }
                ldmx4(al, ad + N_ST_ALO);
#pragma unroll
                for (int nf = 0; nf < 4; nf++) {
                    int pn = nf >> 1, sub = nf & 1;
                    mma_f16(acc[mf][nf], al, bh[pn][sub * 2], bh[pn][sub * 2 + 1]);
                }
            }
        }
        if (c + 1 < NC) {
            const float* vv = (const float*)stA;
            uint32_t ph[4], pl[4];
#pragma unroll
            for (int j = 0; j < 4; j++) {
                float f0 = vv[2 * j], f1 = vv[2 * j + 1];
                float h0 = __half2float(__float2half_rn(f0));
                float h1 = __half2float(__float2half_rn(f1));
                ph[j] = pack_h(f0, f1);
                pl[j] = pack_h(f0 - h0, f1 - h1);
            }
            *(int4*)(smc + no + aRel)            = *(int4*)&ph[0];
            *(int4*)(smc + no + aRel + N_ST_ALO) = *(int4*)&pl[0];
        }
    }

#pragma unroll
    for (int mf = 0; mf < 2; mf++) {
        int r0 = brow + wm * 32 + mf * 16 + gid;
#pragma unroll
        for (int nf = 0; nf < 4; nf++) {
            int col = bcol + wn * 32 + nf * 8 + 2 * tig;
            float b0 = bias[col], b1 = bias[col + 1];
            float v0 = acc[mf][nf][0] + b0;
            float v1 = acc[mf][nf][1] + b1;
            float v2 = acc[mf][nf][2] + b0;
            float v3 = acc[mf][nf][3] + b1;
            if (doRelu) {
                v0 = fmaxf(v0, 0.f); v1 = fmaxf(v1, 0.f);
                v2 = fmaxf(v2, 0.f); v3 = fmaxf(v3, 0.f);
            }
            if (r0 < M)     *(float2*)(out + (size_t)r0 * D_DIM + col)       = make_float2(v0, v1);
            if (r0 + 8 < M) *(float2*)(out + (size_t)(r0 + 8) * D_DIM + col) = make_float2(v2, v3);
        }
    }
}

// ---------------- LayerNorm (+ fused agg init) ----------------
__global__ void __launch_bounds__(128) layernorm_kernel(const float* __restrict__ g,
                                                        const float* __restrict__ gamma,
                                                        const float* __restrict__ beta,
                                                        float* __restrict__ out,
                                                        const float* __restrict__ epsArr,
                                                        int nextLayer,
                                                        float* __restrict__ agg) {
    int row = blockIdx.x, t = threadIdx.x;
    const float4* gp = (const float4*)(g + (size_t)row * D_DIM);
    float4 v = gp[t];
    float s  = v.x + v.y + v.z + v.w;
    float sq = v.x * v.x + v.y * v.y + v.z * v.z + v.w * v.w;
#pragma unroll
    for (int o = 16; o > 0; o >>= 1) {
        s  += __shfl_xor_sync(0xffffffffu, s, o);
        sq += __shfl_xor_sync(0xffffffffu, sq, o);
    }
    __shared__ float red[8];
    int w = t >> 5;
    if ((t & 31) == 0) { red[w] = s; red[4 + w] = sq; }
    __syncthreads();
    s  = red[0] + red[1] + red[2] + red[3];
    sq = red[4] + red[5] + red[6] + red[7];
    float mu  = s * (1.0f / D_DIM);
    float var = sq * (1.0f / D_DIM) - mu * mu;
    float inv = rsqrtf(var + LN_EPS);
    float4 ga = *(const float4*)(gamma + t * 4);
    float4 be = *(const float4*)(beta + t * 4);
    float4 o;
    o.x = (v.x - mu) * inv * ga.x + be.x;
    o.y = (v.y - mu) * inv * ga.y + be.y;
    o.z = (v.z - mu) * inv * ga.z + be.z;
    o.w = (v.w - mu) * inv * ga.w + be.w;
    ((float4*)(out + (size_t)row * D_DIM))[t] = o;
    if (nextLayer < L_LAYERS) {
        float sc = 1.0f + epsArr[nextLayer];
        float4 a;
        a.x = o.x * sc; a.y = o.y * sc; a.z = o.z * sc; a.w = o.w * sc;
        ((float4*)(agg + (size_t)row * D_DIM))[t] = a;
    }
}

// ---------------- launch ----------------
extern "C" void kernel_launch(void* const* d_in, const int* in_sizes, int n_in,
                              void* d_out, int out_size) {
    const float* x     = (const float*)d_in[0];
    const void*  ei    = d_in[1];
    const float* ea    = (const float*)d_in[2];
    const float* We    = (const float*)d_in[3];
    const float* be    = (const float*)d_in[4];
    const float* eps   = (const float*)d_in[5];
    const float* W1    = (const float*)d_in[6];
    const float* b1    = (const float*)d_in[7];
    const float* W2    = (const float*)d_in[8];
    const float* b2    = (const float*)d_in[9];
    const float* gamma = (const float*)d_in[10];
    const float* beta  = (const float*)d_in[11];
    const float* Wf    = (const float*)d_in[12];
    const float* bf    = (const float*)d_in[13];
    float* out = (float*)d_out;

    float *agg, *h, *t, *gg;
    unsigned short *Weh, *W1h, *W2h, *Wfh;
    cudaGetSymbolAddress((void**)&agg, g_agg);
    cudaGetSymbolAddress((void**)&h,   g_h);
    cudaGetSymbolAddress((void**)&t,   g_t);
    cudaGetSymbolAddress((void**)&gg,  g_g);
    cudaGetSymbolAddress((void**)&Weh, g_Weh);
    cudaGetSymbolAddress((void**)&W1h, g_W1h);
    cudaGetSymbolAddress((void**)&W2h, g_W2h);
    cudaGetSymbolAddress((void**)&Wfh, g_Wfh);

    cudaFuncSetAttribute(edge_mma_kernel, cudaFuncAttributeMaxDynamicSharedMemorySize, SMEM_EDGE_T);
    cudaFuncSetAttribute(node_mma_kernel, cudaFuncAttributeMaxDynamicSharedMemorySize, SMEM_NODE_T);

    // ---- preprocessing: edge MMA stays at launch index 3 (profiled) ----
    fused_sort_kernel<<<SORT_BLKS, 256>>>(ei);                                   // 0
    presplit_edges_kernel<<<E_EDGES * (EDGE_DIM / 4) / 256, 256>>>(ea);          // 1
    presplit_w_agg_kernel<<<WPRE_BLKS, 256>>>(We, W1, W2, Wf, x, eps, agg);      // 2

    dim3 gEdge(D_DIM / 128, E_EDGES / 128);                 // (4, 1250)
    dim3 gNode(D_DIM / 128, (N_NODES + 63) / 64);           // (4, 157)
    const size_t WSTEP = (size_t)D_DIM * D_DIM;

    for (int l = 0; l < L_LAYERS; l++) {
        const float* hCur = (l == 0) ? x : h;
        edge_mma_kernel<<<gEdge, 256, SMEM_EDGE_T>>>(                            // 3 = profiled
            Weh + (size_t)l * EDGE_DIM * D_DIM,
            be + (size_t)l * D_DIM, hCur, agg);
        node_mma_kernel<<<gNode, 256, SMEM_NODE_T>>>(
            agg, W1h + l * WSTEP, b1 + (size_t)l * D_DIM, t, N_NODES, 1);
        node_mma_kernel<<<gNode, 256, SMEM_NODE_T>>>(
            t, W2h + l * WSTEP, b2 + (size_t)l * D_DIM, gg, N_NODES, 1);
        layernorm_kernel<<<N_NODES, 128>>>(gg, gamma + (size_t)l * D_DIM,
                                           beta + (size_t)l * D_DIM, h,
                                           eps, l + 1, agg);
    }
    node_mma_kernel<<<gNode, 256, SMEM_NODE_T>>>(h, Wfh, bf, out, N_NODES, 0);
}